// round 1
// baseline (speedup 1.0000x reference)
#include <cuda_runtime.h>

#define NE 50000
#define NP 25000
#define EN 200000
#define D  128
#define NTOT (NE + NP)

// ---------------- device scratch (no allocations allowed) ----------------
__device__ float g_xeA[NE * D];
__device__ float g_xeB[NE * D];
__device__ float g_xpA[NP * D];
__device__ float g_xpB[NP * D];
__device__ float g_hs[NE * D];      // per-type source transform (reused)
__device__ float g_es[NE];
__device__ float g_ed[NE];
__device__ float g_m[NE];           // segment max
__device__ float g_den[NE];         // segment sum
__device__ float g_w[EN];           // logit, then exp weight (in place)
__device__ float g_v[2 * D];        // [vs | vd]
__device__ float g_colsum[D];

// ---------------- small utility kernels ----------------
__global__ void k_zero(float* p, int n) {
    int i = blockIdx.x * blockDim.x + threadIdx.x;
    if (i < n) p[i] = 0.f;
}

__global__ void k_fill_bias(float* __restrict__ out, const float* __restrict__ b1,
                            const float* __restrict__ b2, int nrows) {
    int i = blockIdx.x * blockDim.x + threadIdx.x;
    if (i < nrows * D) {
        int c = i & (D - 1);
        out[i] = b1[c] + b2[c];
    }
}

// vs = W_src @ a_src (row-dot), vd = W_dst @ a_dst. 256 threads: 0..127 -> vs, 128..255 -> vd
__global__ void k_calc_v(const float* __restrict__ Ws, const float* __restrict__ Wd,
                         const float* __restrict__ as_, const float* __restrict__ ad_) {
    int t = threadIdx.x;
    const float* W = (t < D) ? Ws : Wd;
    const float* a = (t < D) ? as_ : ad_;
    int r = t & (D - 1);
    float s = 0.f;
#pragma unroll 8
    for (int k = 0; k < D; k++) s += W[r * D + k] * a[k];
    g_v[t] = s;
}

// out[row] = dot(x[row,:], v)   (one warp per row, float4 + shfl reduce)
__global__ void k_matvec(const float* __restrict__ x, const float* __restrict__ v,
                         float* __restrict__ out, int n) {
    int w = (blockIdx.x * blockDim.x + threadIdx.x) >> 5;
    int lane = threadIdx.x & 31;
    if (w >= n) return;
    float4 a  = ((const float4*)(x + (size_t)w * D))[lane];
    float4 vv = ((const float4*)v)[lane];
    float p = a.x * vv.x + a.y * vv.y + a.z * vv.z + a.w * vv.w;
#pragma unroll
    for (int o = 16; o > 0; o >>= 1) p += __shfl_down_sync(0xffffffffu, p, o);
    if (lane == 0) out[w] = p;
}

// ---------------- GEMM: C[M,128] = A[M,128] @ B[128,128], fp32 ----------------
// 128x128 block tile, BK=16, 256 threads, 8x8 micro-tile per thread.
__global__ __launch_bounds__(256, 2) void k_gemm(const float* __restrict__ A,
                                                 const float* __restrict__ B,
                                                 float* __restrict__ C, int M) {
    __shared__ float As[16][128];  // transposed A tile: As[k][row]
    __shared__ float Bs[16][128];

    int tid  = threadIdx.x;
    int row0 = blockIdx.x * 128;
    int tx = tid & 15, ty = tid >> 4;

    int arow = tid >> 1, acol = (tid & 1) * 8;   // A tile load: 2x float4 per thread
    int brow = tid >> 4, bcol = (tid & 15) * 8;  // B tile load: 2x float4 per thread

    float acc[8][8] = {};
    const float* Aptr = A + (size_t)(row0 + arow) * D;
    bool avalid = (row0 + arow) < M;

    for (int kk = 0; kk < D; kk += 16) {
        float4 a0, a1;
        if (avalid) {
            a0 = *(const float4*)(Aptr + kk + acol);
            a1 = *(const float4*)(Aptr + kk + acol + 4);
        } else {
            a0 = make_float4(0.f, 0.f, 0.f, 0.f);
            a1 = a0;
        }
        As[acol + 0][arow] = a0.x; As[acol + 1][arow] = a0.y;
        As[acol + 2][arow] = a0.z; As[acol + 3][arow] = a0.w;
        As[acol + 4][arow] = a1.x; As[acol + 5][arow] = a1.y;
        As[acol + 6][arow] = a1.z; As[acol + 7][arow] = a1.w;

        *(float4*)&Bs[brow][bcol]     = *(const float4*)(B + (size_t)(kk + brow) * D + bcol);
        *(float4*)&Bs[brow][bcol + 4] = *(const float4*)(B + (size_t)(kk + brow) * D + bcol + 4);
        __syncthreads();

#pragma unroll
        for (int k = 0; k < 16; k++) {
            float4 ra0 = *(const float4*)&As[k][ty * 8];
            float4 ra1 = *(const float4*)&As[k][ty * 8 + 4];
            float4 rb0 = *(const float4*)&Bs[k][tx * 8];
            float4 rb1 = *(const float4*)&Bs[k][tx * 8 + 4];
            float ra[8] = {ra0.x, ra0.y, ra0.z, ra0.w, ra1.x, ra1.y, ra1.z, ra1.w};
            float rb[8] = {rb0.x, rb0.y, rb0.z, rb0.w, rb1.x, rb1.y, rb1.z, rb1.w};
#pragma unroll
            for (int i = 0; i < 8; i++)
#pragma unroll
                for (int j = 0; j < 8; j++) acc[i][j] += ra[i] * rb[j];
        }
        __syncthreads();
    }

#pragma unroll
    for (int i = 0; i < 8; i++) {
        int gr = row0 + ty * 8 + i;
        if (gr < M) {
            float4 o0 = {acc[i][0], acc[i][1], acc[i][2], acc[i][3]};
            float4 o1 = {acc[i][4], acc[i][5], acc[i][6], acc[i][7]};
            *(float4*)(C + (size_t)gr * D + tx * 8)     = o0;
            *(float4*)(C + (size_t)gr * D + tx * 8 + 4) = o1;
        }
    }
}

// ---------------- edge kernels ----------------
// logit = relu(es[src]+ed[dst]); store; segment max via int atomicMax (values >= 0)
__global__ void k_edge_max(const int* __restrict__ src, const int* __restrict__ dst,
                           const float* __restrict__ es, const float* __restrict__ ed,
                           float* __restrict__ logit, float* __restrict__ m) {
    int e = blockIdx.x * blockDim.x + threadIdx.x;
    if (e >= EN) return;
    float l = fmaxf(es[src[e]] + ed[dst[e]], 0.f);
    logit[e] = l;
    atomicMax((int*)(m + dst[e]), __float_as_int(l));
}

// w = exp(logit - m[dst]); segment sum
__global__ void k_edge_exp(const int* __restrict__ dst, float* __restrict__ w,
                           const float* __restrict__ m, float* __restrict__ den) {
    int e = blockIdx.x * blockDim.x + threadIdx.x;
    if (e >= EN) return;
    int d = dst[e];
    float val = expf(w[e] - m[d]);
    w[e] = val;
    atomicAdd(den + d, val);
}

// out[dst] += alpha * hs[src]   (one warp per edge, float4 gather, 4 scalar atomics/lane)
__global__ void k_edge_agg(const int* __restrict__ src, const int* __restrict__ dst,
                           const float* __restrict__ w, const float* __restrict__ den,
                           const float* __restrict__ hs, float* __restrict__ out) {
    int e = (blockIdx.x * blockDim.x + threadIdx.x) >> 5;
    if (e >= EN) return;
    int lane = threadIdx.x & 31;
    int s = src[e], d = dst[e];
    float alpha = w[e] / fmaxf(den[d], 1e-16f);
    float4 v = ((const float4*)(hs + (size_t)s * D))[lane];
    float* o = out + (size_t)d * D + lane * 4;
    atomicAdd(o + 0, alpha * v.x);
    atomicAdd(o + 1, alpha * v.y);
    atomicAdd(o + 2, alpha * v.z);
    atomicAdd(o + 3, alpha * v.w);
}

// ---------------- final reduction ----------------
__global__ void k_colsum(const float* __restrict__ x, int n, float* __restrict__ acc) {
    int c = threadIdx.x;             // 128 threads = 128 columns
    int row0 = blockIdx.x * 64;
    float s = 0.f;
#pragma unroll 4
    for (int r = 0; r < 64; r++) {
        int row = row0 + r;
        if (row < n) s += x[(size_t)row * D + c];
    }
    atomicAdd(acc + c, s);
}

__global__ void k_finalize(const float* __restrict__ colsum, const float* __restrict__ lin_W,
                           const float* __restrict__ lin_b, float* __restrict__ out) {
    if (threadIdx.x == 0) {
        float o0 = lin_b[0], o1 = lin_b[1];
        const float inv = 1.f / (float)NTOT;
        for (int i = 0; i < D; i++) {
            float mv = colsum[i] * inv;
            o0 += mv * lin_W[2 * i];
            o1 += mv * lin_W[2 * i + 1];
        }
        out[0] = o0;
        out[1] = o1;
    }
}

// ---------------- host orchestration ----------------
extern "C" void kernel_launch(void* const* d_in, const int* in_sizes, int n_in,
                              void* d_out, int out_size) {
    const float* x_elem  = (const float*)d_in[0];
    const float* x_proc  = (const float*)d_in[1];
    const float* W_src   = (const float*)d_in[2];   // [3,4,128,128]
    const float* W_dst   = (const float*)d_in[3];
    const float* att_src = (const float*)d_in[4];   // [3,4,128]
    const float* att_dst = (const float*)d_in[5];
    const float* bias    = (const float*)d_in[6];   // [3,4,128]
    const float* lin_W   = (const float*)d_in[7];   // [128,2]
    const float* lin_b   = (const float*)d_in[8];   // [2]
    const int* esrc[4] = {(const int*)d_in[9],  (const int*)d_in[11],
                          (const int*)d_in[13], (const int*)d_in[15]};
    const int* edst[4] = {(const int*)d_in[10], (const int*)d_in[12],
                          (const int*)d_in[14], (const int*)d_in[16]};
    float* out = (float*)d_out;

    float *xeA, *xeB, *xpA, *xpB, *hs, *es, *ed, *m, *den, *w, *v, *colsum;
    cudaGetSymbolAddress((void**)&xeA, g_xeA);
    cudaGetSymbolAddress((void**)&xeB, g_xeB);
    cudaGetSymbolAddress((void**)&xpA, g_xpA);
    cudaGetSymbolAddress((void**)&xpB, g_xpB);
    cudaGetSymbolAddress((void**)&hs,  g_hs);
    cudaGetSymbolAddress((void**)&es,  g_es);
    cudaGetSymbolAddress((void**)&ed,  g_ed);
    cudaGetSymbolAddress((void**)&m,   g_m);
    cudaGetSymbolAddress((void**)&den, g_den);
    cudaGetSymbolAddress((void**)&w,   g_w);
    cudaGetSymbolAddress((void**)&v,   g_v);
    cudaGetSymbolAddress((void**)&colsum, g_colsum);

    for (int l = 0; l < 3; l++) {
        const float* xe_in = (l == 0) ? x_elem : ((l & 1) ? xeB : xeA);
        const float* xp_in = (l == 0) ? x_proc : ((l & 1) ? xpB : xpA);
        float* xe_out = (l & 1) ? xeA : xeB;
        float* xp_out = (l & 1) ? xpA : xpB;

        // xe_new = bias[l,0] + bias[l,3]; xp_new = bias[l,1] + bias[l,2]
        k_fill_bias<<<(NE * D + 255) / 256, 256>>>(xe_out, bias + (size_t)(l * 4 + 0) * D,
                                                   bias + (size_t)(l * 4 + 3) * D, NE);
        k_fill_bias<<<(NP * D + 255) / 256, 256>>>(xp_out, bias + (size_t)(l * 4 + 1) * D,
                                                   bias + (size_t)(l * 4 + 2) * D, NP);

        for (int t = 0; t < 4; t++) {
            // t0: e->e, t1: e->p, t2: p->p, t3: p->e
            const float* xs = (t < 2) ? xe_in : xp_in;
            int Ns          = (t < 2) ? NE : NP;
            const float* xd = (t == 0 || t == 3) ? xe_in : xp_in;
            int Nd          = (t == 0 || t == 3) ? NE : NP;
            float* xout     = (t == 0 || t == 3) ? xe_out : xp_out;

            const float* Ws  = W_src   + (size_t)(l * 4 + t) * D * D;
            const float* Wd  = W_dst   + (size_t)(l * 4 + t) * D * D;
            const float* as_ = att_src + (size_t)(l * 4 + t) * D;
            const float* ad_ = att_dst + (size_t)(l * 4 + t) * D;

            k_calc_v<<<1, 256>>>(Ws, Wd, as_, ad_);
            k_gemm<<<(Ns + 127) / 128, 256>>>(xs, Ws, hs, Ns);
            k_matvec<<<((size_t)Ns * 32 + 255) / 256, 256>>>(xs, v, es, Ns);
            k_matvec<<<((size_t)Nd * 32 + 255) / 256, 256>>>(xd, v + D, ed, Nd);
            k_zero<<<(Nd + 255) / 256, 256>>>(m, Nd);
            k_zero<<<(Nd + 255) / 256, 256>>>(den, Nd);
            k_edge_max<<<(EN + 255) / 256, 256>>>(esrc[t], edst[t], es, ed, w, m);
            k_edge_exp<<<(EN + 255) / 256, 256>>>(edst[t], w, m, den);
            k_edge_agg<<<((size_t)EN * 32 + 255) / 256, 256>>>(esrc[t], edst[t], w, den, hs, xout);
        }
    }

    // after layer 2 (even), results live in xeB / xpB
    k_zero<<<1, 128>>>(colsum, D);
    k_colsum<<<(NE + 63) / 64, 128>>>(xeB, NE, colsum);
    k_colsum<<<(NP + 63) / 64, 128>>>(xpB, NP, colsum);
    k_finalize<<<1, 32>>>(colsum, lin_W, lin_b, out);
}

// round 2
// speedup vs baseline: 1.1762x; 1.1762x over previous
#include <cuda_runtime.h>

#define NE 50000
#define NP 25000
#define EN 200000
#define D  128
#define NTOT (NE + NP)
#define BLK_E ((NE + 127) / 128)   // 391
#define BLK_P ((NP + 127) / 128)   // 196

// ---------------- device scratch ----------------
__device__ float g_xeA[NE * D];
__device__ float g_xeB[NE * D];
__device__ float g_xpA[NP * D];
__device__ float g_xpB[NP * D];
__device__ float g_hs[(2 * NE + 2 * NP) * D];  // per-type source transforms
__device__ float g_es[4 * NE];
__device__ float g_ed[4 * NE];
__device__ float g_m[4 * NE];
__device__ float g_den[4 * NE];
__device__ float g_w[4 * EN];
__device__ float g_vd[4 * D];
__device__ float g_colsum[D];

struct EPtr { const int* src[4]; const int* dst[4]; };

__device__ __forceinline__ size_t hs_off(int t) {
    return (t < 2) ? (size_t)t * NE * D : (size_t)2 * NE * D + (size_t)(t - 2) * NP * D;
}

// ---------------- utility kernels ----------------
__global__ void k_zero2(float* a, float* b, int n) {
    int i = blockIdx.x * blockDim.x + threadIdx.x;
    if (i < n) { a[i] = 0.f; b[i] = 0.f; }
}

__global__ void k_fill_bias(float* __restrict__ out, const float* __restrict__ b1,
                            const float* __restrict__ b2, int nrows) {
    int i = blockIdx.x * blockDim.x + threadIdx.x;
    if (i < nrows * D) {
        int c = i & (D - 1);
        out[i] = b1[c] + b2[c];
    }
}

// vd[t] = W_dst[l,t] @ att_dst[l,t] for all 4 types. 512 threads.
__global__ void k_calc_vd(const float* __restrict__ Wd, const float* __restrict__ ad) {
    int t = threadIdx.x >> 7;
    int r = threadIdx.x & (D - 1);
    const float* W = Wd + (size_t)t * D * D + (size_t)r * D;
    const float* a = ad + (size_t)t * D;
    float s = 0.f;
#pragma unroll 8
    for (int k = 0; k < D; k++) s += W[k] * a[k];
    g_vd[threadIdx.x] = s;
}

// ed[t, row] = dot(x_dst_type(t)[row], vd[t]) for all 4 types, one warp per row.
__global__ void k_matvec_ed(const float* __restrict__ xe, const float* __restrict__ xp) {
    int gw = (blockIdx.x * blockDim.x + threadIdx.x) >> 5;
    int lane = threadIdx.x & 31;
    if (gw >= 2 * NE + 2 * NP) return;
    int t, row;
    const float* x;
    if (gw < NE)                { t = 0; row = gw;                x = xe; }
    else if (gw < NE + NP)      { t = 1; row = gw - NE;           x = xp; }
    else if (gw < NE + 2 * NP)  { t = 2; row = gw - NE - NP;      x = xp; }
    else                        { t = 3; row = gw - NE - 2 * NP;  x = xe; }
    float4 a = ((const float4*)(x + (size_t)row * D))[lane];
    float4 v = ((const float4*)(g_vd + t * D))[lane];
    float p = a.x * v.x + a.y * v.y + a.z * v.z + a.w * v.w;
#pragma unroll
    for (int o = 16; o > 0; o >>= 1) p += __shfl_down_sync(0xffffffffu, p, o);
    if (lane == 0) g_ed[t * NE + row] = p;
}

// ---------------- batched GEMM + fused es epilogue ----------------
// For all 4 types of one layer: hs_t = x_src(t) @ W_src[l,t]; es_t = hs_t @ att_src[l,t]
__global__ __launch_bounds__(256, 2) void k_gemm_es(
    const float* __restrict__ xe, const float* __restrict__ xp,
    const float* __restrict__ Wsrc,   // layer base [4,128,128]
    const float* __restrict__ asrc)   // layer base [4,128]
{
    __shared__ float As[16][128];
    __shared__ float Bs[16][128];
    __shared__ float Rs[128][16];     // es partial reduce

    int bx = blockIdx.x;
    int t, bb;
    if (bx < BLK_E)               { t = 0; bb = bx; }
    else if (bx < 2 * BLK_E)      { t = 1; bb = bx - BLK_E; }
    else if (bx < 2*BLK_E+BLK_P)  { t = 2; bb = bx - 2 * BLK_E; }
    else                          { t = 3; bb = bx - 2 * BLK_E - BLK_P; }

    const float* A = (t < 2) ? xe : xp;
    int M          = (t < 2) ? NE : NP;
    const float* B = Wsrc + (size_t)t * D * D;
    float* C       = g_hs + hs_off(t);
    float* es      = g_es + t * NE;

    int tid  = threadIdx.x;
    int row0 = bb * 128;
    int tx = tid & 15, ty = tid >> 4;

    // a_src slice for this thread's 8 columns
    float as8[8];
#pragma unroll
    for (int j = 0; j < 8; j++) as8[j] = asrc[t * D + tx * 8 + j];

    int arow = tid >> 1, acol = (tid & 1) * 8;
    int brow = tid >> 4, bcol = (tid & 15) * 8;

    float acc[8][8] = {};
    const float* Aptr = A + (size_t)(row0 + arow) * D;
    bool avalid = (row0 + arow) < M;

    for (int kk = 0; kk < D; kk += 16) {
        float4 a0, a1;
        if (avalid) {
            a0 = *(const float4*)(Aptr + kk + acol);
            a1 = *(const float4*)(Aptr + kk + acol + 4);
        } else {
            a0 = make_float4(0.f, 0.f, 0.f, 0.f);
            a1 = a0;
        }
        As[acol + 0][arow] = a0.x; As[acol + 1][arow] = a0.y;
        As[acol + 2][arow] = a0.z; As[acol + 3][arow] = a0.w;
        As[acol + 4][arow] = a1.x; As[acol + 5][arow] = a1.y;
        As[acol + 6][arow] = a1.z; As[acol + 7][arow] = a1.w;

        *(float4*)&Bs[brow][bcol]     = *(const float4*)(B + (size_t)(kk + brow) * D + bcol);
        *(float4*)&Bs[brow][bcol + 4] = *(const float4*)(B + (size_t)(kk + brow) * D + bcol + 4);
        __syncthreads();

#pragma unroll
        for (int k = 0; k < 16; k++) {
            float4 ra0 = *(const float4*)&As[k][ty * 8];
            float4 ra1 = *(const float4*)&As[k][ty * 8 + 4];
            float4 rb0 = *(const float4*)&Bs[k][tx * 8];
            float4 rb1 = *(const float4*)&Bs[k][tx * 8 + 4];
            float ra[8] = {ra0.x, ra0.y, ra0.z, ra0.w, ra1.x, ra1.y, ra1.z, ra1.w};
            float rb[8] = {rb0.x, rb0.y, rb0.z, rb0.w, rb1.x, rb1.y, rb1.z, rb1.w};
#pragma unroll
            for (int i = 0; i < 8; i++)
#pragma unroll
                for (int j = 0; j < 8; j++) acc[i][j] += ra[i] * rb[j];
        }
        __syncthreads();
    }

    // store C + es partials
#pragma unroll
    for (int i = 0; i < 8; i++) {
        int gr = row0 + ty * 8 + i;
        float p = acc[i][0] * as8[0] + acc[i][1] * as8[1] + acc[i][2] * as8[2] + acc[i][3] * as8[3]
                + acc[i][4] * as8[4] + acc[i][5] * as8[5] + acc[i][6] * as8[6] + acc[i][7] * as8[7];
        Rs[ty * 8 + i][tx] = p;
        if (gr < M) {
            float4 o0 = {acc[i][0], acc[i][1], acc[i][2], acc[i][3]};
            float4 o1 = {acc[i][4], acc[i][5], acc[i][6], acc[i][7]};
            *(float4*)(C + (size_t)gr * D + tx * 8)     = o0;
            *(float4*)(C + (size_t)gr * D + tx * 8 + 4) = o1;
        }
    }
    __syncthreads();
    if (tid < 128) {
        float s = 0.f;
#pragma unroll
        for (int x = 0; x < 16; x++) s += Rs[tid][x];
        if (row0 + tid < M) es[row0 + tid] = s;
    }
}

// ---------------- batched edge kernels ----------------
__global__ void k_edge_max_b(EPtr ep) {
    int idx = blockIdx.x * blockDim.x + threadIdx.x;
    if (idx >= 4 * EN) return;
    int t = idx / EN, e = idx - t * EN;
    int s = ep.src[t][e], d = ep.dst[t][e];
    float l = fmaxf(g_es[t * NE + s] + g_ed[t * NE + d], 0.f);
    g_w[t * EN + e] = l;
    atomicMax((int*)(g_m + t * NE + d), __float_as_int(l));
}

__global__ void k_edge_exp_b(EPtr ep) {
    int idx = blockIdx.x * blockDim.x + threadIdx.x;
    if (idx >= 4 * EN) return;
    int t = idx / EN, e = idx - t * EN;
    int d = ep.dst[t][e];
    float val = expf(g_w[t * EN + e] - g_m[t * NE + d]);
    g_w[t * EN + e] = val;
    atomicAdd(g_den + t * NE + d, val);
}

// one warp per edge; vector red.global.add.v4.f32 for the scatter
__global__ void k_edge_agg_b(EPtr ep, float* __restrict__ xe_out, float* __restrict__ xp_out) {
    int gw = (blockIdx.x * blockDim.x + threadIdx.x) >> 5;
    if (gw >= 4 * EN) return;
    int lane = threadIdx.x & 31;
    int t = gw / EN, e = gw - t * EN;
    int s = ep.src[t][e], d = ep.dst[t][e];
    float alpha = g_w[t * EN + e] / fmaxf(g_den[t * NE + d], 1e-16f);
    const float* hrow = g_hs + hs_off(t) + (size_t)s * D;
    float4 v = ((const float4*)hrow)[lane];
    float* out = ((t == 0 || t == 3) ? xe_out : xp_out) + (size_t)d * D + lane * 4;
    asm volatile("red.global.add.v4.f32 [%0], {%1, %2, %3, %4};"
                 :: "l"(out), "f"(alpha * v.x), "f"(alpha * v.y),
                    "f"(alpha * v.z), "f"(alpha * v.w)
                 : "memory");
}

// ---------------- final reduction ----------------
__global__ void k_colsum(const float* __restrict__ x, int n, float* __restrict__ acc) {
    int c = threadIdx.x;
    int row0 = blockIdx.x * 64;
    float s = 0.f;
#pragma unroll 4
    for (int r = 0; r < 64; r++) {
        int row = row0 + r;
        if (row < n) s += x[(size_t)row * D + c];
    }
    atomicAdd(acc + c, s);
}

__global__ void k_zero1(float* p, int n) {
    int i = blockIdx.x * blockDim.x + threadIdx.x;
    if (i < n) p[i] = 0.f;
}

__global__ void k_finalize(const float* __restrict__ colsum, const float* __restrict__ lin_W,
                           const float* __restrict__ lin_b, float* __restrict__ out) {
    if (threadIdx.x == 0) {
        float o0 = lin_b[0], o1 = lin_b[1];
        const float inv = 1.f / (float)NTOT;
        for (int i = 0; i < D; i++) {
            float mv = colsum[i] * inv;
            o0 += mv * lin_W[2 * i];
            o1 += mv * lin_W[2 * i + 1];
        }
        out[0] = o0;
        out[1] = o1;
    }
}

// ---------------- host orchestration ----------------
extern "C" void kernel_launch(void* const* d_in, const int* in_sizes, int n_in,
                              void* d_out, int out_size) {
    const float* x_elem  = (const float*)d_in[0];
    const float* x_proc  = (const float*)d_in[1];
    const float* W_src   = (const float*)d_in[2];
    const float* W_dst   = (const float*)d_in[3];
    const float* att_src = (const float*)d_in[4];
    const float* att_dst = (const float*)d_in[5];
    const float* bias    = (const float*)d_in[6];
    const float* lin_W   = (const float*)d_in[7];
    const float* lin_b   = (const float*)d_in[8];
    EPtr ep;
    ep.src[0] = (const int*)d_in[9];  ep.dst[0] = (const int*)d_in[10];
    ep.src[1] = (const int*)d_in[11]; ep.dst[1] = (const int*)d_in[12];
    ep.src[2] = (const int*)d_in[13]; ep.dst[2] = (const int*)d_in[14];
    ep.src[3] = (const int*)d_in[15]; ep.dst[3] = (const int*)d_in[16];
    float* out = (float*)d_out;

    float *xeA, *xeB, *xpA, *xpB, *m, *den, *colsum;
    cudaGetSymbolAddress((void**)&xeA, g_xeA);
    cudaGetSymbolAddress((void**)&xeB, g_xeB);
    cudaGetSymbolAddress((void**)&xpA, g_xpA);
    cudaGetSymbolAddress((void**)&xpB, g_xpB);
    cudaGetSymbolAddress((void**)&m,   g_m);
    cudaGetSymbolAddress((void**)&den, g_den);
    cudaGetSymbolAddress((void**)&colsum, g_colsum);

    const int nblk_gemm = 2 * BLK_E + 2 * BLK_P;

    for (int l = 0; l < 3; l++) {
        const float* xe_in = (l == 0) ? x_elem : ((l & 1) ? xeB : xeA);
        const float* xp_in = (l == 0) ? x_proc : ((l & 1) ? xpB : xpA);
        float* xe_out = (l & 1) ? xeA : xeB;
        float* xp_out = (l & 1) ? xpA : xpB;

        k_fill_bias<<<(NE * D + 255) / 256, 256>>>(xe_out, bias + (size_t)(l * 4 + 0) * D,
                                                   bias + (size_t)(l * 4 + 3) * D, NE);
        k_fill_bias<<<(NP * D + 255) / 256, 256>>>(xp_out, bias + (size_t)(l * 4 + 1) * D,
                                                   bias + (size_t)(l * 4 + 2) * D, NP);
        k_zero2<<<(4 * NE + 255) / 256, 256>>>(m, den, 4 * NE);

        k_calc_vd<<<1, 512>>>(W_dst + (size_t)l * 4 * D * D, att_dst + (size_t)l * 4 * D);
        k_gemm_es<<<nblk_gemm, 256>>>(xe_in, xp_in, W_src + (size_t)l * 4 * D * D,
                                      att_src + (size_t)l * 4 * D);
        k_matvec_ed<<<((2 * NE + 2 * NP) * 32 + 255) / 256, 256>>>(xe_in, xp_in);

        k_edge_max_b<<<(4 * EN + 255) / 256, 256>>>(ep);
        k_edge_exp_b<<<(4 * EN + 255) / 256, 256>>>(ep);
        k_edge_agg_b<<<((size_t)4 * EN * 32 + 255) / 256, 256>>>(ep, xe_out, xp_out);
    }

    k_zero1<<<1, 128>>>(colsum, D);
    k_colsum<<<(NE + 63) / 64, 128>>>(xeB, NE, colsum);
    k_colsum<<<(NP + 63) / 64, 128>>>(xpB, NP, colsum);
    k_finalize<<<1, 32>>>(colsum, lin_W, lin_b, out);
}

// round 3
// speedup vs baseline: 2.4002x; 2.0406x over previous
#include <cuda_runtime.h>

#define NE 50000
#define NP 25000
#define EN 200000
#define D  128
#define NTOT (NE + NP)
#define BINS (2 * NE + 2 * NP)         // 150000
#define NSCAN ((BINS + 1023) / 1024)   // 147
#define BLK_E ((NE + 127) / 128)
#define BLK_P ((NP + 127) / 128)

// ---------------- device scratch ----------------
__device__ float g_xeA[NE * D];
__device__ float g_xeB[NE * D];
__device__ float g_xpA[NP * D];
__device__ float g_xpB[NP * D];
__device__ float g_hs[(2 * NE + 2 * NP) * D];
__device__ float g_es[4 * NE];
__device__ float g_vd[4 * D];
__device__ float g_colsum[D];
__device__ int   g_deg[BINS];
__device__ int   g_rowptr[BINS];
__device__ int   g_cur[BINS];
__device__ int   g_bsum[NSCAN];
__device__ int   g_csr_src[4 * EN];

struct EPtr { const int* src[4]; const int* dst[4]; };

__device__ __forceinline__ size_t hs_off(int t) {
    return (t < 2) ? (size_t)t * NE * D : (size_t)2 * NE * D + (size_t)(t - 2) * NP * D;
}
__device__ __forceinline__ int bin_base(int t) {
    // t0: elem dst, t1: proc dst, t2: proc dst, t3: elem dst
    const int b[4] = {0, NE, NE + NP, NE + 2 * NP};
    return b[t];
}

// ---------------- CSR build (once per call) ----------------
__global__ void k_zero_int(int* p, int n) {
    int i = blockIdx.x * blockDim.x + threadIdx.x;
    if (i < n) p[i] = 0;
}

__global__ void k_hist(EPtr ep) {
    int idx = blockIdx.x * blockDim.x + threadIdx.x;
    if (idx >= 4 * EN) return;
    int t = idx / EN, e = idx - t * EN;
    atomicAdd(&g_deg[bin_base(t) + ep.dst[t][e]], 1);
}

__global__ void k_scan1() {
    __shared__ int sh[256];
    int b = blockIdx.x;
    int base = b * 1024 + threadIdx.x * 4;
    int v[4];
#pragma unroll
    for (int i = 0; i < 4; i++) v[i] = (base + i < BINS) ? g_deg[base + i] : 0;
    int tsum = v[0] + v[1] + v[2] + v[3];
    sh[threadIdx.x] = tsum;
    __syncthreads();
    int val = tsum;
    for (int off = 1; off < 256; off <<= 1) {
        int y = (threadIdx.x >= off) ? sh[threadIdx.x - off] : 0;
        __syncthreads();
        val += y;
        sh[threadIdx.x] = val;
        __syncthreads();
    }
    int run = val - tsum;   // exclusive prefix of this thread's 4 items
#pragma unroll
    for (int i = 0; i < 4; i++) {
        if (base + i < BINS) g_rowptr[base + i] = run;
        run += v[i];
    }
    if (threadIdx.x == 255) g_bsum[b] = val;
}

__global__ void k_scan2() {
    if (threadIdx.x == 0) {
        int run = 0;
        for (int i = 0; i < NSCAN; i++) {
            int t = g_bsum[i];
            g_bsum[i] = run;
            run += t;
        }
    }
}

__global__ void k_scan3() {
    int i = blockIdx.x * blockDim.x + threadIdx.x;
    if (i < BINS) {
        int r = g_rowptr[i] + g_bsum[i >> 10];
        g_rowptr[i] = r;
        g_cur[i] = r;
    }
}

__global__ void k_scatter(EPtr ep) {
    int idx = blockIdx.x * blockDim.x + threadIdx.x;
    if (idx >= 4 * EN) return;
    int t = idx / EN, e = idx - t * EN;
    int pos = atomicAdd(&g_cur[bin_base(t) + ep.dst[t][e]], 1);
    g_csr_src[pos] = ep.src[t][e];
}

// ---------------- vd = W_dst @ att_dst, one warp per (t, row) ----------------
__global__ void k_calc_vd(const float* __restrict__ Wd, const float* __restrict__ ad) {
    int gw = (blockIdx.x * blockDim.x + threadIdx.x) >> 5;
    int lane = threadIdx.x & 31;
    if (gw >= 4 * D) return;
    int t = gw >> 7, r = gw & (D - 1);
    float4 w = ((const float4*)(Wd + (size_t)(t * D + r) * D))[lane];
    float4 a = ((const float4*)(ad + (size_t)t * D))[lane];
    float p = w.x * a.x + w.y * a.y + w.z * a.z + w.w * a.w;
#pragma unroll
    for (int o = 16; o > 0; o >>= 1) p += __shfl_down_sync(0xffffffffu, p, o);
    if (lane == 0) g_vd[t * D + r] = p;
}

// ---------------- batched GEMM + fused es epilogue ----------------
__global__ __launch_bounds__(256, 2) void k_gemm_es(
    const float* __restrict__ xe, const float* __restrict__ xp,
    const float* __restrict__ Wsrc, const float* __restrict__ asrc)
{
    __shared__ float As[16][128];
    __shared__ float Bs[16][128];
    __shared__ float Rs[128][16];

    int bx = blockIdx.x;
    int t, bb;
    if (bx < BLK_E)                   { t = 0; bb = bx; }
    else if (bx < 2 * BLK_E)          { t = 1; bb = bx - BLK_E; }
    else if (bx < 2 * BLK_E + BLK_P)  { t = 2; bb = bx - 2 * BLK_E; }
    else                              { t = 3; bb = bx - 2 * BLK_E - BLK_P; }

    const float* A = (t < 2) ? xe : xp;
    int M          = (t < 2) ? NE : NP;
    const float* B = Wsrc + (size_t)t * D * D;
    float* C       = g_hs + hs_off(t);
    float* es      = g_es + t * NE;

    int tid  = threadIdx.x;
    int row0 = bb * 128;
    int tx = tid & 15, ty = tid >> 4;

    float as8[8];
#pragma unroll
    for (int j = 0; j < 8; j++) as8[j] = asrc[t * D + tx * 8 + j];

    int arow = tid >> 1, acol = (tid & 1) * 8;
    int brow = tid >> 4, bcol = (tid & 15) * 8;

    float acc[8][8] = {};
    const float* Aptr = A + (size_t)(row0 + arow) * D;
    bool avalid = (row0 + arow) < M;

    for (int kk = 0; kk < D; kk += 16) {
        float4 a0, a1;
        if (avalid) {
            a0 = *(const float4*)(Aptr + kk + acol);
            a1 = *(const float4*)(Aptr + kk + acol + 4);
        } else {
            a0 = make_float4(0.f, 0.f, 0.f, 0.f);
            a1 = a0;
        }
        As[acol + 0][arow] = a0.x; As[acol + 1][arow] = a0.y;
        As[acol + 2][arow] = a0.z; As[acol + 3][arow] = a0.w;
        As[acol + 4][arow] = a1.x; As[acol + 5][arow] = a1.y;
        As[acol + 6][arow] = a1.z; As[acol + 7][arow] = a1.w;

        *(float4*)&Bs[brow][bcol]     = *(const float4*)(B + (size_t)(kk + brow) * D + bcol);
        *(float4*)&Bs[brow][bcol + 4] = *(const float4*)(B + (size_t)(kk + brow) * D + bcol + 4);
        __syncthreads();

#pragma unroll
        for (int k = 0; k < 16; k++) {
            float4 ra0 = *(const float4*)&As[k][ty * 8];
            float4 ra1 = *(const float4*)&As[k][ty * 8 + 4];
            float4 rb0 = *(const float4*)&Bs[k][tx * 8];
            float4 rb1 = *(const float4*)&Bs[k][tx * 8 + 4];
            float ra[8] = {ra0.x, ra0.y, ra0.z, ra0.w, ra1.x, ra1.y, ra1.z, ra1.w};
            float rb[8] = {rb0.x, rb0.y, rb0.z, rb0.w, rb1.x, rb1.y, rb1.z, rb1.w};
#pragma unroll
            for (int i = 0; i < 8; i++)
#pragma unroll
                for (int j = 0; j < 8; j++) acc[i][j] += ra[i] * rb[j];
        }
        __syncthreads();
    }

#pragma unroll
    for (int i = 0; i < 8; i++) {
        int gr = row0 + ty * 8 + i;
        float p = acc[i][0] * as8[0] + acc[i][1] * as8[1] + acc[i][2] * as8[2] + acc[i][3] * as8[3]
                + acc[i][4] * as8[4] + acc[i][5] * as8[5] + acc[i][6] * as8[6] + acc[i][7] * as8[7];
        Rs[ty * 8 + i][tx] = p;
        if (gr < M) {
            float4 o0 = {acc[i][0], acc[i][1], acc[i][2], acc[i][3]};
            float4 o1 = {acc[i][4], acc[i][5], acc[i][6], acc[i][7]};
            *(float4*)(C + (size_t)gr * D + tx * 8)     = o0;
            *(float4*)(C + (size_t)gr * D + tx * 8 + 4) = o1;
        }
    }
    __syncthreads();
    if (tid < 128) {
        float s = 0.f;
#pragma unroll
        for (int x = 0; x < 16; x++) s += Rs[tid][x];
        if (row0 + tid < M) es[row0 + tid] = s;
    }
}

// ---------------- fused per-dst aggregation (no atomics) ----------------
// one warp per destination node; handles both incoming edge types + bias; single store.
__device__ __forceinline__ void gat_accum(int t, int d, const float4& xrow, int lane,
                                          float4& acc, float& den) {
    int bin = bin_base(t) + d;
    int start = g_rowptr[bin];
    int deg   = g_deg[bin];
    if (deg == 0) { den = 0.f; return; }

    // ed = dot(xrow_lane_slice, vd[t]) reduced across warp (butterfly -> all lanes)
    float4 v = ((const float4*)(g_vd + t * D))[lane];
    float ed = xrow.x * v.x + xrow.y * v.y + xrow.z * v.z + xrow.w * v.w;
#pragma unroll
    for (int o = 16; o > 0; o >>= 1) ed += __shfl_xor_sync(0xffffffffu, ed, o);

    const float* es_t = g_es + t * NE;
    // pass A: max logit (lanes strided over edges); logits >= 0, init 0 matches reference
    float mymax = 0.f;
    for (int e = start + lane; e < start + deg; e += 32) {
        int s = g_csr_src[e];
        mymax = fmaxf(mymax, fmaxf(es_t[s] + ed, 0.f));
    }
#pragma unroll
    for (int o = 16; o > 0; o >>= 1) mymax = fmaxf(mymax, __shfl_xor_sync(0xffffffffu, mymax, o));

    // pass B: weighted accumulation (serial over edges; all lanes share scalar work)
    const float* hs_t = g_hs + hs_off(t);
    for (int e = start; e < start + deg; e++) {
        int s = g_csr_src[e];
        float logit = fmaxf(es_t[s] + ed, 0.f);
        float w = __expf(logit - mymax);
        den += w;
        float4 h = ((const float4*)(hs_t + (size_t)s * D))[lane];
        acc.x += w * h.x; acc.y += w * h.y; acc.z += w * h.z; acc.w += w * h.w;
    }
}

__global__ __launch_bounds__(256) void k_agg(
    const float* __restrict__ xe_in, const float* __restrict__ xp_in,
    float* __restrict__ xe_out, float* __restrict__ xp_out,
    const float* __restrict__ bias)   // layer base [4,128]
{
    int gw = (blockIdx.x * blockDim.x + threadIdx.x) >> 5;
    int lane = threadIdx.x & 31;
    if (gw >= NTOT) return;

    int tA, tB, d;
    const float* xin;
    float* xout;
    const float *b1, *b2;
    if (gw < NE) { tA = 0; tB = 3; d = gw;       xin = xe_in; xout = xe_out; b1 = bias;         b2 = bias + 3 * D; }
    else         { tA = 1; tB = 2; d = gw - NE;  xin = xp_in; xout = xp_out; b1 = bias + D;     b2 = bias + 2 * D; }

    float4 xrow = ((const float4*)(xin + (size_t)d * D))[lane];

    float4 accA = {0.f, 0.f, 0.f, 0.f}, accB = {0.f, 0.f, 0.f, 0.f};
    float denA = 0.f, denB = 0.f;
    gat_accum(tA, d, xrow, lane, accA, denA);
    gat_accum(tB, d, xrow, lane, accB, denB);

    float ia = 1.f / fmaxf(denA, 1e-16f);
    float ib = 1.f / fmaxf(denB, 1e-16f);
    float4 bb1 = ((const float4*)b1)[lane];
    float4 bb2 = ((const float4*)b2)[lane];
    float4 o;
    o.x = bb1.x + bb2.x + accA.x * ia + accB.x * ib;
    o.y = bb1.y + bb2.y + accA.y * ia + accB.y * ib;
    o.z = bb1.z + bb2.z + accA.z * ia + accB.z * ib;
    o.w = bb1.w + bb2.w + accA.w * ia + accB.w * ib;
    ((float4*)(xout + (size_t)d * D))[lane] = o;
}

// ---------------- final reduction ----------------
__global__ void k_colsum(const float* __restrict__ x, int n, float* __restrict__ acc) {
    int c = threadIdx.x;
    int row0 = blockIdx.x * 64;
    float s = 0.f;
#pragma unroll 4
    for (int r = 0; r < 64; r++) {
        int row = row0 + r;
        if (row < n) s += x[(size_t)row * D + c];
    }
    atomicAdd(acc + c, s);
}

__global__ void k_zero1(float* p, int n) {
    int i = blockIdx.x * blockDim.x + threadIdx.x;
    if (i < n) p[i] = 0.f;
}

__global__ void k_finalize(const float* __restrict__ colsum, const float* __restrict__ lin_W,
                           const float* __restrict__ lin_b, float* __restrict__ out) {
    if (threadIdx.x == 0) {
        float o0 = lin_b[0], o1 = lin_b[1];
        const float inv = 1.f / (float)NTOT;
        for (int i = 0; i < D; i++) {
            float mv = colsum[i] * inv;
            o0 += mv * lin_W[2 * i];
            o1 += mv * lin_W[2 * i + 1];
        }
        out[0] = o0;
        out[1] = o1;
    }
}

// ---------------- host orchestration ----------------
extern "C" void kernel_launch(void* const* d_in, const int* in_sizes, int n_in,
                              void* d_out, int out_size) {
    const float* x_elem  = (const float*)d_in[0];
    const float* x_proc  = (const float*)d_in[1];
    const float* W_src   = (const float*)d_in[2];
    const float* W_dst   = (const float*)d_in[3];
    const float* att_src = (const float*)d_in[4];
    const float* att_dst = (const float*)d_in[5];
    const float* bias    = (const float*)d_in[6];
    const float* lin_W   = (const float*)d_in[7];
    const float* lin_b   = (const float*)d_in[8];
    EPtr ep;
    ep.src[0] = (const int*)d_in[9];  ep.dst[0] = (const int*)d_in[10];
    ep.src[1] = (const int*)d_in[11]; ep.dst[1] = (const int*)d_in[12];
    ep.src[2] = (const int*)d_in[13]; ep.dst[2] = (const int*)d_in[14];
    ep.src[3] = (const int*)d_in[15]; ep.dst[3] = (const int*)d_in[16];
    float* out = (float*)d_out;

    float *xeA, *xeB, *xpA, *xpB, *colsum;
    int *deg;
    cudaGetSymbolAddress((void**)&xeA, g_xeA);
    cudaGetSymbolAddress((void**)&xeB, g_xeB);
    cudaGetSymbolAddress((void**)&xpA, g_xpA);
    cudaGetSymbolAddress((void**)&xpB, g_xpB);
    cudaGetSymbolAddress((void**)&colsum, g_colsum);
    cudaGetSymbolAddress((void**)&deg, g_deg);

    // ---- CSR build (edges shared by all 3 layers) ----
    k_zero_int<<<(BINS + 255) / 256, 256>>>(deg, BINS);
    k_hist<<<(4 * EN + 255) / 256, 256>>>(ep);
    k_scan1<<<NSCAN, 256>>>();
    k_scan2<<<1, 32>>>();
    k_scan3<<<(BINS + 255) / 256, 256>>>();
    k_scatter<<<(4 * EN + 255) / 256, 256>>>(ep);

    const int nblk_gemm = 2 * BLK_E + 2 * BLK_P;

    for (int l = 0; l < 3; l++) {
        const float* xe_in = (l == 0) ? x_elem : ((l & 1) ? xeB : xeA);
        const float* xp_in = (l == 0) ? x_proc : ((l & 1) ? xpB : xpA);
        float* xe_out = (l & 1) ? xeA : xeB;
        float* xp_out = (l & 1) ? xpA : xpB;

        k_calc_vd<<<(4 * D * 32 + 255) / 256, 256>>>(W_dst + (size_t)l * 4 * D * D,
                                                     att_dst + (size_t)l * 4 * D);
        k_gemm_es<<<nblk_gemm, 256>>>(xe_in, xp_in, W_src + (size_t)l * 4 * D * D,
                                      att_src + (size_t)l * 4 * D);
        k_agg<<<(NTOT * 32 + 255) / 256, 256>>>(xe_in, xp_in, xe_out, xp_out,
                                                bias + (size_t)l * 4 * D);
    }

    k_zero1<<<1, 128>>>(colsum, D);
    k_colsum<<<(NE + 63) / 64, 128>>>(xeB, NE, colsum);
    k_colsum<<<(NP + 63) / 64, 128>>>(xpB, NP, colsum);
    k_finalize<<<1, 32>>>(colsum, lin_W, lin_b, out);
}